// round 17
// baseline (speedup 1.0000x reference)
#include <cuda_runtime.h>
#include <cuda_bf16.h>
#include <cstdint>

#define BB  4
#define NN  4096
#define NBK 16
#define CD  128
#define HID 64
#define ROWS (BB*NN)            // 16384
#define GROWS (BB*NN*NBK)       // 262144
#define PAIRS (BB*NBK)          // 64
#define NSPLIT 16
#define BPITCH 136              // bf16 tile pitch (272 B rows)
#define HPITCH 72               // hs tile pitch (144 B rows)

// ---------------- scratch (device globals; no allocation allowed) ----------
__device__ float g_qkv [ROWS*3*CD];                 // 25 MB (K/V cols used)
__device__ unsigned short g_qb[ROWS][2][CD];        // prescaled Qn bf16 hi/lo
__device__ float g_kvp [NSPLIT][PAIRS*CD*CD];       // split partials 64 MB
__device__ unsigned short g_kvb[PAIRS][2][128*BPITCH]; // bf16 hi/lo kv images
__device__ unsigned short g_w2b[2][HID*BPITCH];     // W2^T images
__device__ unsigned short g_wm1b[4][2][128*BPITCH]; // Wm1^T chunk images [c][o]
__device__ unsigned short g_wm2b[4][2][128*BPITCH]; // Wm2^T chunk images [o][d]
__device__ unsigned short g_wqb[3][2][128*BPITCH];  // Wqkv^T chunk images [c][o]
__device__ int   g_idx64;

typedef unsigned long long u64;
__device__ __forceinline__ float4 ld4(const float* p) { return *(const float4*)p; }
__device__ __forceinline__ int ld_idx(const void* p, size_t pos) {
    if (g_idx64) return (int)((const long long*)p)[pos];
    return ((const int*)p)[pos];
}
__device__ __forceinline__ uint32_t smem_u32(const void* p) {
    uint32_t a;
    asm("{ .reg .u64 t; cvta.to.shared.u64 t, %1; cvt.u32.u64 %0, t; }" : "=r"(a) : "l"(p));
    return a;
}
__device__ __forceinline__ void bf_split(float x, unsigned short& h, unsigned short& l) {
    __nv_bfloat16 bh = __float2bfloat16(x);
    h = __bfloat16_as_ushort(bh);
    l = __bfloat16_as_ushort(__float2bfloat16(x - __bfloat162float(bh)));
}

#define LDSM_X4(r0,r1,r2,r3, a) \
    asm volatile("ldmatrix.sync.aligned.m8n8.x4.shared.b16 {%0,%1,%2,%3}, [%4];" \
        : "=r"(r0),"=r"(r1),"=r"(r2),"=r"(r3) : "r"(a))
#define LDSM_X4T(r0,r1,r2,r3, a) \
    asm volatile("ldmatrix.sync.aligned.m8n8.x4.trans.shared.b16 {%0,%1,%2,%3}, [%4];" \
        : "=r"(r0),"=r"(r1),"=r"(r2),"=r"(r3) : "r"(a))
#define MMA_BF16(d, a0,a1,a2,a3, b0,b1) \
    asm volatile("mma.sync.aligned.m16n8k16.row.col.f32.bf16.bf16.f32 " \
        "{%0,%1,%2,%3}, {%4,%5,%6,%7}, {%8,%9}, {%0,%1,%2,%3};" \
        : "+f"((d)[0]),"+f"((d)[1]),"+f"((d)[2]),"+f"((d)[3]) \
        : "r"(a0),"r"(a1),"r"(a2),"r"(a3), "r"(b0),"r"(b1))

// ---------------- idx dtype autodetect -------------------------------------
__global__ void k_detect(const unsigned int* __restrict__ w) {
    __shared__ int any;
    if (threadIdx.x == 0) any = 0;
    __syncthreads();
    unsigned int v = w[1 + 2 * threadIdx.x];
    if (v != 0u) any = 1;
    __syncthreads();
    if (threadIdx.x == 0) g_idx64 = (any ? 0 : 1);
}

// ---------------- K0: weight bf16 hi/lo pre-splits (runs first) -------------
__global__ void __launch_bounds__(256) k_wsplit(const float* __restrict__ W2,
                                                const float* __restrict__ Wm1,
                                                const float* __restrict__ Wm2,
                                                const float* __restrict__ Wqkv) {
    const int v = blockIdx.x;
    const int w = blockIdx.y;
    const int tid = (int)(blockIdx.z * 256 + threadIdx.x);
    const int stride = 1024;
    if (w == 0) {
        for (int e = tid; e < CD * HID; e += stride) {
            int j = e >> 7, c = e & 127;
            float x = W2[(size_t)c * HID + j];
            __nv_bfloat16 bh = __float2bfloat16(x);
            unsigned short bits = v == 0 ? __bfloat16_as_ushort(bh)
                : __bfloat16_as_ushort(__float2bfloat16(x - __bfloat162float(bh)));
            g_w2b[v][j * BPITCH + c] = bits;
        }
    } else if (w <= 4) {
        const int oc = w - 1;
        for (int e = tid; e < CD * CD; e += stride) {
            int c = e >> 7, o = e & 127;
            float x = Wm1[(size_t)(oc * 128 + o) * CD + c];
            __nv_bfloat16 bh = __float2bfloat16(x);
            unsigned short bits = v == 0 ? __bfloat16_as_ushort(bh)
                : __bfloat16_as_ushort(__float2bfloat16(x - __bfloat162float(bh)));
            g_wm1b[oc][v][c * BPITCH + o] = bits;
        }
    } else if (w <= 8) {
        const int oc = w - 5;
        for (int e = tid; e < CD * CD; e += stride) {
            int ol = e >> 7, d = e & 127;
            float x = Wm2[(size_t)d * (4 * CD) + oc * 128 + ol];
            __nv_bfloat16 bh = __float2bfloat16(x);
            unsigned short bits = v == 0 ? __bfloat16_as_ushort(bh)
                : __bfloat16_as_ushort(__float2bfloat16(x - __bfloat162float(bh)));
            g_wm2b[oc][v][ol * BPITCH + d] = bits;
        }
    } else {
        const int oc = w - 9;
        for (int e = tid; e < CD * CD; e += stride) {
            int c = e >> 7, o = e & 127;
            float x = Wqkv[(size_t)(oc * 128 + o) * CD + c];
            __nv_bfloat16 bh = __float2bfloat16(x);
            unsigned short bits = v == 0 ? __bfloat16_as_ushort(bh)
                : __bfloat16_as_ushort(__float2bfloat16(x - __bfloat162float(bh)));
            g_wqb[oc][v][c * BPITCH + o] = bits;
        }
    }
}

// ---------------- K1: qkv via mma.sync (oc==0 fuses Q-norm -> g_qb) ---------
#define QK_A_H 0
#define QK_A_L (32*BPITCH*2)
#define QK_B_H (2*32*BPITCH*2)
#define QK_B_L (QK_B_H + 128*BPITCH*2)
#define QK_SMEM (QK_B_H + 2*128*BPITCH*2)

__global__ void __launch_bounds__(256, 2) k_qkv_mma(const float* __restrict__ x) {
    extern __shared__ __align__(16) unsigned char dsm[];
    const uint32_t sb = smem_u32(dsm);
    const int tid = threadIdx.x;
    const int wid = tid >> 5, lane = tid & 31;
    const int row0 = blockIdx.x * 128;
    const int b = row0 >> 12;
    const int n0 = row0 & (NN - 1);
    const int oc = blockIdx.y;
    const int m0 = wid * 16;

    {
        uint4* Bh = (uint4*)(dsm + QK_B_H);
        uint4* Bl = (uint4*)(dsm + QK_B_L);
        const uint4* sh = (const uint4*)&g_wqb[oc][0][0];
        const uint4* sl = (const uint4*)&g_wqb[oc][1][0];
        for (int e = tid; e < (128 * BPITCH * 2) / 16; e += 256) {
            Bh[e] = sh[e];
            Bl[e] = sl[e];
        }
    }

    const int rowSel = lane & 15;
    const int colSel = (lane >> 4) << 3;
    const uint32_t aTerm = (uint32_t)((rowSel * BPITCH + m0 + colSel) * 2);
    const uint32_t bTerm = (uint32_t)((rowSel * BPITCH + colSel) * 2);
    const int g = lane >> 2, t = lane & 3;

    float facc[16][4] = {};

    for (int cstep = 0; cstep < 4; cstep++) {
        __syncthreads();
        {
            unsigned short* Ah = (unsigned short*)(dsm + QK_A_H);
            unsigned short* Al = (unsigned short*)(dsm + QK_A_L);
#pragma unroll
            for (int p = 0; p < 16; p++) {
                int v = tid + p * 256;
                int cc = v >> 7, n = v & 127;
                float xv = x[((size_t)b * CD + cstep * 32 + cc) * NN + n0 + n];
                unsigned short h, l;
                bf_split(xv, h, l);
                Ah[cc * BPITCH + n] = h;
                Al[cc * BPITCH + n] = l;
            }
        }
        __syncthreads();
#pragma unroll
        for (int c2 = 0; c2 < 2; c2++) {
            const uint32_t cOffA = (uint32_t)(c2 * 16 * BPITCH * 2);
            uint32_t t0, t1, t2, t3;
            uint32_t ah0, ah1, ah2, ah3, al0, al1, al2, al3;
            LDSM_X4T(t0, t1, t2, t3, sb + QK_A_H + aTerm + cOffA);
            ah0 = t0; ah1 = t2; ah2 = t1; ah3 = t3;
            LDSM_X4T(t0, t1, t2, t3, sb + QK_A_L + aTerm + cOffA);
            al0 = t0; al1 = t2; al2 = t1; al3 = t3;
            const uint32_t bBase = sb + QK_B_H + bTerm
                + (uint32_t)((cstep * 32 + c2 * 16) * BPITCH * 2);
#pragma unroll
            for (int dblk = 0; dblk < 8; dblk++) {
                uint32_t bh0, bh1, bh2, bh3, bl0, bl1, bl2, bl3;
                uint32_t bAddr = bBase + (uint32_t)(dblk * 16 * 2);
                LDSM_X4T(bh0, bh1, bh2, bh3, bAddr);
                LDSM_X4T(bl0, bl1, bl2, bl3, bAddr + (QK_B_L - QK_B_H));
                float* d0 = facc[dblk * 2];
                float* d1 = facc[dblk * 2 + 1];
                MMA_BF16(d0, ah0, ah1, ah2, ah3, bh0, bh1);
                MMA_BF16(d1, ah0, ah1, ah2, ah3, bh2, bh3);
                MMA_BF16(d0, al0, al1, al2, al3, bh0, bh1);
                MMA_BF16(d1, al0, al1, al2, al3, bh2, bh3);
                MMA_BF16(d0, ah0, ah1, ah2, ah3, bl0, bl1);
                MMA_BF16(d1, ah0, ah1, ah2, ah3, bl2, bl3);
            }
        }
    }
    if (oc == 0) {
        // fused Q-norm: rows m0+g and m0+8+g; quad (t=0..3) holds the full row
        float s1 = 0.f, s2 = 0.f;
#pragma unroll
        for (int dt = 0; dt < 16; dt++) {
            s1 += facc[dt][0] * facc[dt][0] + facc[dt][1] * facc[dt][1];
            s2 += facc[dt][2] * facc[dt][2] + facc[dt][3] * facc[dt][3];
        }
        s1 += __shfl_xor_sync(0xffffffffu, s1, 1);
        s1 += __shfl_xor_sync(0xffffffffu, s1, 2);
        s2 += __shfl_xor_sync(0xffffffffu, s2, 1);
        s2 += __shfl_xor_sync(0xffffffffu, s2, 2);
        float sc1 = 1.0f / fmaxf(sqrtf(s1), 1e-12f);
        float sc2 = 1.0f / fmaxf(sqrtf(s2), 1e-12f);
        int r1 = row0 + m0 + g, r2 = row0 + m0 + 8 + g;
#pragma unroll
        for (int dt = 0; dt < 16; dt++) {
            int col = dt * 8 + t * 2;
            unsigned short h0, l0, h1, l1, h2, l2, h3, l3;
            bf_split(facc[dt][0] * sc1, h0, l0);
            bf_split(facc[dt][1] * sc1, h1, l1);
            bf_split(facc[dt][2] * sc2, h2, l2);
            bf_split(facc[dt][3] * sc2, h3, l3);
            *(uint32_t*)&g_qb[r1][0][col] = (uint32_t)h0 | ((uint32_t)h1 << 16);
            *(uint32_t*)&g_qb[r1][1][col] = (uint32_t)l0 | ((uint32_t)l1 << 16);
            *(uint32_t*)&g_qb[r2][0][col] = (uint32_t)h2 | ((uint32_t)h3 << 16);
            *(uint32_t*)&g_qb[r2][1][col] = (uint32_t)l2 | ((uint32_t)l3 << 16);
        }
    } else {
#pragma unroll
        for (int dt = 0; dt < 16; dt++) {
            int col = oc * 128 + dt * 8 + t * 2;
            size_t r1 = (size_t)(row0 + m0 + g) * (3 * CD) + col;
            size_t r2 = (size_t)(row0 + m0 + 8 + g) * (3 * CD) + col;
            *(float2*)&g_qkv[r1] = make_float2(facc[dt][0], facc[dt][1]);
            *(float2*)&g_qkv[r2] = make_float2(facc[dt][2], facc[dt][3]);
        }
    }
}

// ---------------- K3: FUSED pos-MLP + kv outer product via mma.sync ---------
#define KV_KN_H 0
#define KV_KN_L (32*BPITCH*2)
#define KV_VR_H (2*32*BPITCH*2)
#define KV_VR_L (3*32*BPITCH*2)
#define KV_W2_H (4*32*BPITCH*2)
#define KV_W2_L (KV_W2_H + HID*BPITCH*2)
#define KV_HS_H (KV_W2_H + 2*HID*BPITCH*2)
#define KV_HS_L (KV_HS_H + 32*HPITCH*2)
#define KV_PE   (KV_HS_H + 2*32*HPITCH*2)
#define KV_SMEM (KV_PE + 32*132*4)
#define PEP 132

__global__ void __launch_bounds__(256, 2) k_kv_mma(
    const float* __restrict__ pos, const void* __restrict__ idx,
    const float* __restrict__ dist,
    const float* __restrict__ W1, const float* __restrict__ b1,
    const float* __restrict__ b2) {
    extern __shared__ __align__(16) unsigned char dsm[];
    __shared__ float W1s[HID * 10];
    __shared__ float b1s[HID];
    __shared__ float b2s[CD];
    __shared__ float feats[32][12];
    __shared__ int   jr[32];
    const uint32_t sb = smem_u32(dsm);
    const int p = blockIdx.y;
    const int s = blockIdx.x;
    const int b = p >> 4, kslot = p & 15;
    const int tid = threadIdx.x;
    const int lane = tid & 31, warp = tid >> 5;
    const int c4 = lane * 4;
    const int m0 = warp * 16;

    for (int v = tid; v < HID * 10; v += 256) W1s[v] = W1[v];
    if (tid < HID) b1s[tid] = b1[tid];
    if (tid < CD)  b2s[tid] = b2[tid];
    {
        uint4* Wh = (uint4*)(dsm + KV_W2_H);
        uint4* Wl = (uint4*)(dsm + KV_W2_L);
        const uint4* sh = (const uint4*)&g_w2b[0][0];
        const uint4* sl = (const uint4*)&g_w2b[1][0];
        for (int e = tid; e < (HID * BPITCH * 2) / 16; e += 256) {
            Wh[e] = sh[e];
            Wl[e] = sl[e];
        }
    }

    const int rowSel = lane & 15;
    const int colSel = (lane >> 4) << 3;
    const uint32_t aTerm = (uint32_t)((rowSel * BPITCH + m0 + colSel) * 2);
    const uint32_t bTerm = (uint32_t)((rowSel * BPITCH + colSel) * 2);
    const int mt = warp & 1, ng = warp >> 1;
    const uint32_t aTermP = (uint32_t)(((mt * 16 + rowSel) * HPITCH + colSel) * 2);
    const uint32_t bTermP = (uint32_t)((rowSel * BPITCH + ng * 32 + colSel) * 2);
    const int g = lane >> 2, t = lane & 3;

    float facc[16][4] = {};

    const int n0 = s * (NN / NSPLIT);
    const int NSTEP = (NN / NSPLIT) / 32;
    for (int step = 0; step < NSTEP; step++) {
        const int nbase = n0 + step * 32;
        __syncthreads();
        if (tid < 32) {
            int n = nbase + tid;
            size_t gg = ((size_t)(b * NN + n)) * NBK + kslot;
            int j = ld_idx(idx, gg);
            jr[tid] = j;
            const float* pc = &pos[((size_t)b * NN + n) * 3];
            const float* pn = &pos[((size_t)b * NN + j) * 3];
            float a0 = pc[0], a1 = pc[1], a2 = pc[2];
            float q0 = pn[0], q1 = pn[1], q2 = pn[2];
            feats[tid][0] = a0;  feats[tid][1] = a1;  feats[tid][2] = a2;
            feats[tid][3] = q0;  feats[tid][4] = q1;  feats[tid][5] = q2;
            feats[tid][6] = a0 - q0; feats[tid][7] = a1 - q1; feats[tid][8] = a2 - q2;
            feats[tid][9] = dist[gg];
        }
        __syncthreads();
        {
            unsigned short* Hh = (unsigned short*)(dsm + KV_HS_H);
            unsigned short* Hl = (unsigned short*)(dsm + KV_HS_L);
#pragma unroll
            for (int pp = 0; pp < 8; pp++) {
                int v = tid + pp * 256;
                int j = v & 63, r = v >> 6;
                float sm = b1s[j];
#pragma unroll
                for (int i = 0; i < 10; i++) sm += feats[r][i] * W1s[j * 10 + i];
                sm = fmaxf(sm, 0.0f);
                unsigned short h, l;
                bf_split(sm, h, l);
                Hh[r * HPITCH + j] = h;
                Hl[r * HPITCH + j] = l;
            }
        }
        __syncthreads();
        {
            float pacc[2][2][4] = {};
#pragma unroll
            for (int cc = 0; cc < 4; cc++) {
                uint32_t ah0, ah1, ah2, ah3, al0, al1, al2, al3;
                uint32_t aAddr = sb + KV_HS_H + aTermP + (uint32_t)(cc * 16 * 2);
                LDSM_X4(ah0, ah1, ah2, ah3, aAddr);
                LDSM_X4(al0, al1, al2, al3, aAddr + (KV_HS_L - KV_HS_H));
                uint32_t bBase = sb + KV_W2_H + bTermP + (uint32_t)(cc * 16 * BPITCH * 2);
#pragma unroll
                for (int d2 = 0; d2 < 2; d2++) {
                    uint32_t bh0, bh1, bh2, bh3, bl0, bl1, bl2, bl3;
                    uint32_t bAddr = bBase + (uint32_t)(d2 * 16 * 2);
                    LDSM_X4T(bh0, bh1, bh2, bh3, bAddr);
                    LDSM_X4T(bl0, bl1, bl2, bl3, bAddr + (KV_W2_L - KV_W2_H));
                    float* d0 = pacc[d2][0];
                    float* d1 = pacc[d2][1];
                    MMA_BF16(d0, ah0, ah1, ah2, ah3, bh0, bh1);
                    MMA_BF16(d1, ah0, ah1, ah2, ah3, bh2, bh3);
                    MMA_BF16(d0, al0, al1, al2, al3, bh0, bh1);
                    MMA_BF16(d1, al0, al1, al2, al3, bh2, bh3);
                    MMA_BF16(d0, ah0, ah1, ah2, ah3, bl0, bl1);
                    MMA_BF16(d1, ah0, ah1, ah2, ah3, bl2, bl3);
                }
            }
            float* PE = (float*)(dsm + KV_PE);
#pragma unroll
            for (int d2 = 0; d2 < 2; d2++)
#pragma unroll
                for (int hf = 0; hf < 2; hf++) {
                    int col = ng * 32 + d2 * 16 + hf * 8 + t * 2;
                    float bx = b2s[col], by = b2s[col + 1];
                    int r1 = mt * 16 + g, r2 = mt * 16 + 8 + g;
                    *(float2*)&PE[r1 * PEP + col] =
                        make_float2(pacc[d2][hf][0] + bx, pacc[d2][hf][1] + by);
                    *(float2*)&PE[r2 * PEP + col] =
                        make_float2(pacc[d2][hf][2] + bx, pacc[d2][hf][3] + by);
                }
        }
        __syncthreads();
        {
            unsigned short* KnH = (unsigned short*)(dsm + KV_KN_H);
            unsigned short* KnL = (unsigned short*)(dsm + KV_KN_L);
            unsigned short* VrH = (unsigned short*)(dsm + KV_VR_H);
            unsigned short* VrL = (unsigned short*)(dsm + KV_VR_L);
            const float* PE = (const float*)(dsm + KV_PE);
#pragma unroll
            for (int rr = 0; rr < 4; rr++) {
                int row = warp * 4 + rr;
                int j = jr[row];
                float4 pe = ld4(&PE[row * PEP + c4]);
                const float* qrow = &g_qkv[((size_t)b * NN + j) * (3 * CD)];
                float4 kg = ld4(&qrow[CD + c4]);
                float4 vg = ld4(&qrow[2 * CD + c4]);
                float k0 = kg.x + pe.x, k1 = kg.y + pe.y, k2 = kg.z + pe.z, k3 = kg.w + pe.w;
                float v0 = fmaxf(vg.x + pe.x, 0.f), v1 = fmaxf(vg.y + pe.y, 0.f);
                float v2 = fmaxf(vg.z + pe.z, 0.f), v3 = fmaxf(vg.w + pe.w, 0.f);
                float ss = k0 * k0 + k1 * k1 + k2 * k2 + k3 * k3;
#pragma unroll
                for (int o = 16; o; o >>= 1) ss += __shfl_xor_sync(0xffffffffu, ss, o);
                float sc = 1.0f / fmaxf(sqrtf(ss), 1e-12f);
                k0 *= sc; k1 *= sc; k2 *= sc; k3 *= sc;
                unsigned short kh[4], kl[4], vh[4], vl[4];
                bf_split(k0, kh[0], kl[0]); bf_split(k1, kh[1], kl[1]);
                bf_split(k2, kh[2], kl[2]); bf_split(k3, kh[3], kl[3]);
                bf_split(v0, vh[0], vl[0]); bf_split(v1, vh[1], vl[1]);
                bf_split(v2, vh[2], vl[2]); bf_split(v3, vh[3], vl[3]);
                int off = row * BPITCH + c4;
                *(uint2*)&KnH[off] = make_uint2((uint32_t)kh[0] | ((uint32_t)kh[1] << 16),
                                                (uint32_t)kh[2] | ((uint32_t)kh[3] << 16));
                *(uint2*)&KnL[off] = make_uint2((uint32_t)kl[0] | ((uint32_t)kl[1] << 16),
                                                (uint32_t)kl[2] | ((uint32_t)kl[3] << 16));
                *(uint2*)&VrH[off] = make_uint2((uint32_t)vh[0] | ((uint32_t)vh[1] << 16),
                                                (uint32_t)vh[2] | ((uint32_t)vh[3] << 16));
                *(uint2*)&VrL[off] = make_uint2((uint32_t)vl[0] | ((uint32_t)vl[1] << 16),
                                                (uint32_t)vl[2] | ((uint32_t)vl[3] << 16));
            }
        }
        __syncthreads();
#pragma unroll
        for (int cc = 0; cc < 2; cc++) {
            const uint32_t cOff = (uint32_t)(cc * 16 * BPITCH * 2);
            uint32_t t0, t1, t2, t3;
            uint32_t ah0, ah1, ah2, ah3, al0, al1, al2, al3;
            LDSM_X4T(t0, t1, t2, t3, sb + KV_KN_H + aTerm + cOff);
            ah0 = t0; ah1 = t2; ah2 = t1; ah3 = t3;
            LDSM_X4T(t0, t1, t2, t3, sb + KV_KN_L + aTerm + cOff);
            al0 = t0; al1 = t2; al2 = t1; al3 = t3;
#pragma unroll
            for (int dblk = 0; dblk < 8; dblk++) {
                uint32_t bh0, bh1, bh2, bh3, bl0, bl1, bl2, bl3;
                uint32_t bOff = bTerm + cOff + (uint32_t)(dblk * 16 * 2);
                LDSM_X4T(bh0, bh1, bh2, bh3, sb + KV_VR_H + bOff);
                LDSM_X4T(bl0, bl1, bl2, bl3, sb + KV_VR_L + bOff);
                float* d0 = facc[dblk * 2];
                float* d1 = facc[dblk * 2 + 1];
                MMA_BF16(d0, ah0, ah1, ah2, ah3, bh0, bh1);
                MMA_BF16(d1, ah0, ah1, ah2, ah3, bh2, bh3);
                MMA_BF16(d0, al0, al1, al2, al3, bh0, bh1);
                MMA_BF16(d1, al0, al1, al2, al3, bh2, bh3);
                MMA_BF16(d0, ah0, ah1, ah2, ah3, bl0, bl1);
                MMA_BF16(d1, ah0, ah1, ah2, ah3, bl2, bl3);
            }
        }
    }
    float* op = &g_kvp[s][(size_t)p * CD * CD];
#pragma unroll
    for (int dt = 0; dt < 16; dt++) {
        int col = dt * 8 + t * 2;
        *(float2*)&op[(size_t)(m0 + g) * CD + col]     = make_float2(facc[dt][0], facc[dt][1]);
        *(float2*)&op[(size_t)(m0 + 8 + g) * CD + col] = make_float2(facc[dt][2], facc[dt][3]);
    }
}

// ---------------- K3b: reduce partials + split to bf16 hi/lo (4-way) --------
__global__ void __launch_bounds__(256) k_redsplit() {
    const int p = blockIdx.x;
    const int e0 = (int)blockIdx.y * 4096;
    const int tid = threadIdx.x;
    for (int e = e0 + tid; e < e0 + 4096; e += 256) {
        int c = e >> 7, d = e & 127;
        float s = 0.0f;
#pragma unroll
        for (int t = 0; t < NSPLIT; t++) s += g_kvp[t][(size_t)p * CD * CD + e];
        unsigned short h, l;
        bf_split(s, h, l);
        g_kvb[p][0][c * BPITCH + d] = h;
        g_kvb[p][1][c * BPITCH + d] = l;
    }
}

// ---------------- K4: FUSED agg + out-MLP via mma.sync ----------------------
#define MLP_A0 0
#define MLP_A1 34816
#define MLP_B0 69632
#define MLP_B1 104448
#define MLP_H0 139264
#define MLP_H1 174080
#define MLP_SMEM 208896
#define EP 129

__global__ void __launch_bounds__(256, 1) k_aggmlp_mma(
    const void* __restrict__ idx,
    const float* __restrict__ bm1, const float* __restrict__ bm2,
    const float* __restrict__ x, float* __restrict__ out) {
    extern __shared__ __align__(16) unsigned char dsm[];
    __shared__ int jr[128];
    __shared__ float bm1s[4 * CD];
    __shared__ float bm2s[CD];
    const uint32_t sb = smem_u32(dsm);
    const int tid = threadIdx.x;
    const int wid = tid >> 5, lane = tid & 31;
    const int row0 = blockIdx.x * 128;
    const int b = row0 >> 12;
    const int n0 = row0 & (NN - 1);
    const int m0 = wid * 16;

    if (tid < CD) bm2s[tid] = bm2[tid];
    for (int v = tid; v < 4 * CD; v += 256) bm1s[v] = bm1[v];

    const int rowSel = lane & 15;
    const int colSel = (lane >> 4) << 3;
    const uint32_t aTerm = (uint32_t)(((m0 + rowSel) * BPITCH + colSel) * 2);
    const uint32_t bTerm = (uint32_t)((rowSel * BPITCH + colSel) * 2);
    const int g = lane >> 2, t = lane & 3;
    const int arow = tid >> 1, ahalf = tid & 1;

    // ===== agg phase =====
    float facc[16][4] = {};
    for (int k = 0; k < NBK; k++) {
        __syncthreads();
        if (tid < 128) {
            jr[tid] = ld_idx(idx, ((size_t)(row0 + tid)) * NBK + k);
        }
        __syncthreads();
        {
            int j = b * NN + jr[arow];
            const uint4* srcH = (const uint4*)&g_qb[j][0][ahalf * 64];
            const uint4* srcL = (const uint4*)&g_qb[j][1][ahalf * 64];
            uint4* dH = (uint4*)(dsm + MLP_A0 + (uint32_t)((arow * BPITCH + ahalf * 64) * 2));
            uint4* dL = (uint4*)(dsm + MLP_A1 + (uint32_t)((arow * BPITCH + ahalf * 64) * 2));
#pragma unroll
            for (int q = 0; q < 8; q++) {
                dH[q] = srcH[q];
                dL[q] = srcL[q];
            }
        }
        {
            const int p = b * NBK + k;
            uint4* Bh = (uint4*)(dsm + MLP_B0);
            uint4* Bl = (uint4*)(dsm + MLP_B1);
            const uint4* sh = (const uint4*)&g_kvb[p][0][0];
            const uint4* sl = (const uint4*)&g_kvb[p][1][0];
            for (int e = tid; e < (128 * BPITCH * 2) / 16; e += 256) {
                Bh[e] = sh[e];
                Bl[e] = sl[e];
            }
        }
        __syncthreads();
#pragma unroll 1
        for (int cc = 0; cc < 8; cc++) {
            uint32_t ah0, ah1, ah2, ah3, al0, al1, al2, al3;
            uint32_t aAddr = sb + MLP_A0 + aTerm + (uint32_t)(cc * 16 * 2);
            LDSM_X4(ah0, ah1, ah2, ah3, aAddr);
            LDSM_X4(al0, al1, al2, al3, aAddr + (MLP_A1 - MLP_A0));
            uint32_t bBase = sb + MLP_B0 + bTerm + (uint32_t)(cc * 16 * BPITCH * 2);
#pragma unroll
            for (int dblk = 0; dblk < 8; dblk++) {
                uint32_t bh0, bh1, bh2, bh3, bl0, bl1, bl2, bl3;
                uint32_t bAddr = bBase + (uint32_t)(dblk * 16 * 2);
                LDSM_X4T(bh0, bh1, bh2, bh3, bAddr);
                LDSM_X4T(bl0, bl1, bl2, bl3, bAddr + (MLP_B1 - MLP_B0));
                float* d0 = facc[dblk * 2];
                float* d1 = facc[dblk * 2 + 1];
                MMA_BF16(d0, ah0, ah1, ah2, ah3, bh0, bh1);
                MMA_BF16(d1, ah0, ah1, ah2, ah3, bh2, bh3);
                MMA_BF16(d0, al0, al1, al2, al3, bh0, bh1);
                MMA_BF16(d1, al0, al1, al2, al3, bh2, bh3);
                MMA_BF16(d0, ah0, ah1, ah2, ah3, bl0, bl1);
                MMA_BF16(d1, ah0, ah1, ah2, ah3, bl2, bl3);
            }
        }
    }
    // ===== transition: agg (x 1/N) -> bf16 hi/lo A tiles (own rows) =====
    {
        const float inv = 1.0f / (float)NN;
        unsigned short* Ah = (unsigned short*)(dsm + MLP_A0);
        unsigned short* Al = (unsigned short*)(dsm + MLP_A1);
#pragma unroll
        for (int dt = 0; dt < 16; dt++) {
            int col = dt * 8 + t * 2;
            float a0 = facc[dt][0] * inv, a1 = facc[dt][1] * inv;
            float a2 = facc[dt][2] * inv, a3 = facc[dt][3] * inv;
            unsigned short h0, l0, h1, l1, h2, l2, h3, l3;
            bf_split(a0, h0, l0); bf_split(a1, h1, l1);
            bf_split(a2, h2, l2); bf_split(a3, h3, l3);
            int r1 = m0 + g, r2 = m0 + 8 + g;
            *(uint32_t*)&Ah[r1 * BPITCH + col] = (uint32_t)h0 | ((uint32_t)h1 << 16);
            *(uint32_t*)&Al[r1 * BPITCH + col] = (uint32_t)l0 | ((uint32_t)l1 << 16);
            *(uint32_t*)&Ah[r2 * BPITCH + col] = (uint32_t)h2 | ((uint32_t)h3 << 16);
            *(uint32_t*)&Al[r2 * BPITCH + col] = (uint32_t)l2 | ((uint32_t)l3 << 16);
        }
    }
    // ===== MLP phase =====
    float facc2[16][4] = {};
    for (int oc = 0; oc < 4; oc++) {
        __syncthreads();
        {
            uint4* Bh = (uint4*)(dsm + MLP_B0);
            uint4* Bl = (uint4*)(dsm + MLP_B1);
            const uint4* sh = (const uint4*)&g_wm1b[oc][0][0];
            const uint4* sl = (const uint4*)&g_wm1b[oc][1][0];
            for (int e = tid; e < (128 * BPITCH * 2) / 16; e += 256) {
                Bh[e] = sh[e];
                Bl[e] = sl[e];
            }
        }
        __syncthreads();
        float facc1[16][4] = {};
#pragma unroll 1
        for (int cc = 0; cc < 8; cc++) {
            uint32_t ah0, ah1, ah2, ah3, al0, al1, al2, al3;
            uint32_t aAddr = sb + MLP_A0 + aTerm + (uint32_t)(cc * 16 * 2);
            LDSM_X4(ah0, ah1, ah2, ah3, aAddr);
            LDSM_X4(al0, al1, al2, al3, aAddr + (MLP_A1 - MLP_A0));
            uint32_t bBase = sb + MLP_B0 + bTerm + (uint32_t)(cc * 16 * BPITCH * 2);
#pragma unroll
            for (int dblk = 0; dblk < 8; dblk++) {
                uint32_t bh0, bh1, bh2, bh3, bl0, bl1, bl2, bl3;
                uint32_t bAddr = bBase + (uint32_t)(dblk * 16 * 2);
                LDSM_X4T(bh0, bh1, bh2, bh3, bAddr);
                LDSM_X4T(bl0, bl1, bl2, bl3, bAddr + (MLP_B1 - MLP_B0));
                float* d0 = facc1[dblk * 2];
                float* d1 = facc1[dblk * 2 + 1];
                MMA_BF16(d0, ah0, ah1, ah2, ah3, bh0, bh1);
                MMA_BF16(d1, ah0, ah1, ah2, ah3, bh2, bh3);
                MMA_BF16(d0, al0, al1, al2, al3, bh0, bh1);
                MMA_BF16(d1, al0, al1, al2, al3, bh2, bh3);
                MMA_BF16(d0, ah0, ah1, ah2, ah3, bl0, bl1);
                MMA_BF16(d1, ah0, ah1, ah2, ah3, bl2, bl3);
            }
        }
        {
            unsigned short* Hh = (unsigned short*)(dsm + MLP_H0);
            unsigned short* Hl = (unsigned short*)(dsm + MLP_H1);
#pragma unroll
            for (int dt = 0; dt < 16; dt++) {
                int col = dt * 8 + t * 2;
                float bx = bm1s[oc * 128 + col], by = bm1s[oc * 128 + col + 1];
                float h0 = fmaxf(facc1[dt][0] + bx, 0.f);
                float h1 = fmaxf(facc1[dt][1] + by, 0.f);
                float h2 = fmaxf(facc1[dt][2] + bx, 0.f);
                float h3 = fmaxf(facc1[dt][3] + by, 0.f);
                unsigned short hh0, hl0, hh1, hl1, hh2, hl2, hh3, hl3;
                bf_split(h0, hh0, hl0); bf_split(h1, hh1, hl1);
                bf_split(h2, hh2, hl2); bf_split(h3, hh3, hl3);
                int r1 = m0 + g, r2 = m0 + 8 + g;
                *(uint32_t*)&Hh[r1 * BPITCH + col] = (uint32_t)hh0 | ((uint32_t)hh1 << 16);
                *(uint32_t*)&Hl[r1 * BPITCH + col] = (uint32_t)hl0 | ((uint32_t)hl1 << 16);
                *(uint32_t*)&Hh[r2 * BPITCH + col] = (uint32_t)hh2 | ((uint32_t)hh3 << 16);
                *(uint32_t*)&Hl[r2 * BPITCH + col] = (uint32_t)hl2 | ((uint32_t)hl3 << 16);
            }
        }
        __syncthreads();
        {
            uint4* Bh = (uint4*)(dsm + MLP_B0);
            uint4* Bl = (uint4*)(dsm + MLP_B1);
            const uint4* sh = (const uint4*)&g_wm2b[oc][0][0];
            const uint4* sl = (const uint4*)&g_wm2b[oc][1][0];
            for (int e = tid; e < (128 * BPITCH * 2) / 16; e += 256) {
                Bh[e] = sh[e];
                Bl[e] = sl[e];
            }
        }
        __syncthreads();
#pragma unroll 1
        for (int cc = 0; cc < 8; cc++) {
            uint32_t ah0, ah1, ah2, ah3, al0, al1, al2, al3;
            uint32_t aAddr = sb + MLP_H0 + aTerm + (uint32_t)(cc * 16 * 2);
            LDSM_X4(ah0, ah1, ah2, ah3, aAddr);
            LDSM_X4(al0, al1, al2, al3, aAddr + (MLP_H1 - MLP_H0));
            uint32_t bBase = sb + MLP_B0 + bTerm + (uint32_t)(cc * 16 * BPITCH * 2);
#pragma unroll
            for (int dblk = 0; dblk < 8; dblk++) {
                uint32_t bh0, bh1, bh2, bh3, bl0, bl1, bl2, bl3;
                uint32_t bAddr = bBase + (uint32_t)(dblk * 16 * 2);
                LDSM_X4T(bh0, bh1, bh2, bh3, bAddr);
                LDSM_X4T(bl0, bl1, bl2, bl3, bAddr + (MLP_B1 - MLP_B0));
                float* d0 = facc2[dblk * 2];
                float* d1 = facc2[dblk * 2 + 1];
                MMA_BF16(d0, ah0, ah1, ah2, ah3, bh0, bh1);
                MMA_BF16(d1, ah0, ah1, ah2, ah3, bh2, bh3);
                MMA_BF16(d0, al0, al1, al2, al3, bh0, bh1);
                MMA_BF16(d1, al0, al1, al2, al3, bh2, bh3);
                MMA_BF16(d0, ah0, ah1, ah2, ah3, bl0, bl1);
                MMA_BF16(d1, ah0, ah1, ah2, ah3, bl2, bl3);
            }
        }
    }
    __syncthreads();
    {
        float* Cst = (float*)(dsm + MLP_A0);
#pragma unroll
        for (int dt = 0; dt < 16; dt++) {
            int col = dt * 8 + t * 2;
            float bx = bm2s[col], by = bm2s[col + 1];
            int r1 = m0 + g, r2 = m0 + 8 + g;
            Cst[r1 * EP + col]     = facc2[dt][0] + bx;
            Cst[r1 * EP + col + 1] = facc2[dt][1] + by;
            Cst[r2 * EP + col]     = facc2[dt][2] + bx;
            Cst[r2 * EP + col + 1] = facc2[dt][3] + by;
        }
    }
    __syncthreads();
    {
        const float* Cst = (const float*)(dsm + MLP_A0);
        for (int v = tid; v < 128 * CD; v += 256) {
            int dd = v >> 7, nn = v & 127;
            size_t oa = ((size_t)b * CD + dd) * NN + n0 + nn;
            out[oa] = Cst[nn * EP + dd] + x[oa];
        }
    }
}

// ---------------- launcher ---------------------------------------------------
extern "C" void kernel_launch(void* const* d_in, const int* in_sizes, int n_in,
                              void* d_out, int out_size) {
    (void)in_sizes; (void)n_in; (void)out_size;
    const float* pos  = (const float*)d_in[0];
    const float* x    = (const float*)d_in[1];
    const void*  idx  = d_in[2];
    const float* dist = (const float*)d_in[3];
    const float* Wqkv = (const float*)d_in[4];
    const float* W1   = (const float*)d_in[5];
    const float* b1   = (const float*)d_in[6];
    const float* W2   = (const float*)d_in[7];
    const float* b2   = (const float*)d_in[8];
    const float* Wm1  = (const float*)d_in[9];
    const float* bm1  = (const float*)d_in[10];
    const float* Wm2  = (const float*)d_in[11];
    const float* bm2  = (const float*)d_in[12];
    float* out = (float*)d_out;

    cudaFuncSetAttribute(k_qkv_mma,    cudaFuncAttributeMaxDynamicSharedMemorySize, QK_SMEM);
    cudaFuncSetAttribute(k_kv_mma,     cudaFuncAttributeMaxDynamicSharedMemorySize, KV_SMEM);
    cudaFuncSetAttribute(k_aggmlp_mma, cudaFuncAttributeMaxDynamicSharedMemorySize, MLP_SMEM);

    k_detect   <<<1, 256>>>((const unsigned int*)idx);
    k_wsplit   <<<dim3(2, 12, 4), 256>>>(W2, Wm1, Wm2, Wqkv);
    k_qkv_mma  <<<dim3(ROWS / 128, 3), 256, QK_SMEM>>>(x);
    k_kv_mma   <<<dim3(NSPLIT, PAIRS), 256, KV_SMEM>>>(pos, idx, dist, W1, b1, b2);
    k_redsplit <<<dim3(PAIRS, 4), 256>>>();
    k_aggmlp_mma<<<ROWS / 128, 256, MLP_SMEM>>>(idx, bm1, bm2, x, out);
}